// round 13
// baseline (speedup 1.0000x reference)
#include <cuda_runtime.h>
#include <cstdint>

#define B_    2
#define NH_   8
#define N_    4096
#define D_    64
#define K2_   49
#define V_F4  784          // D*K2/4
#define THREADS 128
#define ROWS  8            // rows per CTA in av_stream
#define GW    4            // rows per warp in gemv
#define GR    16           // rows per CTA in gemv (4 warps * 4 rows)

// 12.8 MB scratch for precomputed attention logits  [B,NH,N,K2]
__device__ float g_attn[(size_t)B_ * NH_ * N_ * K2_];

// ---------------------------------------------------------------------------
// helpers
// ---------------------------------------------------------------------------
__device__ __forceinline__ uint32_t smem_u32(const void* p) {
    return (uint32_t)__cvta_generic_to_shared(p);
}
__device__ __forceinline__ void cp16(uint32_t dst, const void* src) {
    asm volatile("cp.async.cg.shared.global [%0], [%1], 16;\n" :: "r"(dst), "l"(src));
}
__device__ __forceinline__ void cp4(uint32_t dst, const void* src) {
    asm volatile("cp.async.ca.shared.global [%0], [%1], 4;\n" :: "r"(dst), "l"(src));
}
__device__ __forceinline__ void cp_commit() {
    asm volatile("cp.async.commit_group;\n" ::: "memory");
}
template <int NPend>
__device__ __forceinline__ void cp_wait() {
    asm volatile("cp.async.wait_group %0;\n" :: "n"(NPend) : "memory");
}

// ---------------------------------------------------------------------------
// Kernel 1 (gemv, LDS-free): warp = 4 rows, lanes = k; tokens LDGs are
// coalesced and reused across the 4 rows; q reads are 1-sector broadcasts.
// ---------------------------------------------------------------------------
__global__ __launch_bounds__(THREADS)
void attn_gemv_rt(const float* __restrict__ q_norm,      // [B,NH,N,D]
                  const float* __restrict__ attn_local,  // [B,NH,N,K2]
                  const float* __restrict__ tokens,      // [NH,D,K2]
                  const float* __restrict__ bias)        // [NH,N,K2]
{
    const int t    = threadIdx.x;
    const int w    = t >> 5;
    const int lane = t & 31;
    const int row0 = blockIdx.x * GR + w * GW;       // 4 consecutive rows
    const int h    = (row0 >> 12) & (NH_ - 1);
    const float* tok_h = tokens + h * (D_ * K2_);

    const int  k0 = lane;                            // chunk 0
    const int  k1 = 32 + lane;                       // chunk 1 (valid if <49)
    const bool v1 = (k1 < K2_);

    const float* q0 = q_norm + (size_t)row0 * D_;

    float acc[GW][2];
#pragma unroll
    for (int rr = 0; rr < GW; rr++) { acc[rr][0] = 0.f; acc[rr][1] = 0.f; }

#pragma unroll 4
    for (int d = 0; d < D_; d++) {
        const float tk0 = __ldg(tok_h + d * K2_ + k0);             // coalesced
        const float tk1 = v1 ? __ldg(tok_h + d * K2_ + k1) : 0.f;  // coalesced
#pragma unroll
        for (int rr = 0; rr < GW; rr++) {
            const float qv = __ldg(q0 + rr * D_ + d);              // broadcast
            acc[rr][0] = fmaf(qv, tk0, acc[rr][0]);
            acc[rr][1] = fmaf(qv, tk1, acc[rr][1]);
        }
    }

    // epilogue: += attn_local + bias, write (lands in L2; consumed next kernel)
    const int n0 = row0 & (N_ - 1);
#pragma unroll
    for (int rr = 0; rr < GW; rr++) {
        const size_t base  = (size_t)(row0 + rr) * K2_;
        const size_t bbase = ((size_t)h * N_ + n0 + rr) * K2_;
        g_attn[base + k0] = acc[rr][0] + __ldg(attn_local + base + k0)
                                       + __ldg(bias + bbase + k0);
        if (v1)
            g_attn[base + k1] = acc[rr][1] + __ldg(attn_local + base + k1)
                                           + __ldg(bias + bbase + k1);
    }
}

// ---------------------------------------------------------------------------
// Kernel 2 (UNCHANGED: 129.5us @ 83% DRAM, verified 3x)
// ---------------------------------------------------------------------------
struct __align__(16) Stage {
    float4 v[V_F4];        // 12544 B
    float  a[K2_];         // 196 B
    float  pad[3];         // sizeof = 12752 (16B multiple)
};

__global__ __launch_bounds__(THREADS)
void av_stream_kernel(const float* __restrict__ v_local,     // [B,NH,N,D,K2]
                      float* __restrict__ out)               // [B,NH,N,D]
{
    __shared__ Stage st[2];

    const int t    = threadIdx.x;
    const int row0 = blockIdx.x * ROWS;

    auto prefetch = [&](int s, int row) {
        const float4* vrow = reinterpret_cast<const float4*>(v_local) + (size_t)row * V_F4;
        uint32_t vdst = smem_u32(st[s].v);
#pragma unroll
        for (int i = 0; i < 6; i++)
            cp16(vdst + (uint32_t)(t + THREADS * i) * 16u, vrow + t + THREADS * i);
        if (t < V_F4 - 6 * THREADS)                   // 16 leftover float4
            cp16(vdst + (uint32_t)(t + 6 * THREADS) * 16u, vrow + t + 6 * THREADS);

        if (t < K2_)
            cp4(smem_u32(st[s].a) + (uint32_t)t * 4u, g_attn + (size_t)row * K2_ + t);
        cp_commit();
    };

    prefetch(0, row0);

    for (int r = 0; r < ROWS; r++) {
        if (r + 1 < ROWS) {
            prefetch((r + 1) & 1, row0 + r + 1);
            cp_wait<1>();
        } else {
            cp_wait<0>();
        }
        __syncthreads();                              // stage r&1 ready

        const Stage& S = st[r & 1];

        if (t < D_) {
            const float* vd = reinterpret_cast<const float*>(S.v) + t * K2_;
            float acc0 = 0.f, acc1 = 0.f;
#pragma unroll
            for (int k = 0; k < 48; k += 2) {
                acc0 = fmaf(S.a[k + 0], vd[k + 0], acc0);
                acc1 = fmaf(S.a[k + 1], vd[k + 1], acc1);
            }
            acc0 = fmaf(S.a[48], vd[48], acc0);
            out[(size_t)(row0 + r) * D_ + t] = acc0 + acc1;
        }

        __syncthreads();                              // readers done before overwrite
    }
}

// ---------------------------------------------------------------------------
extern "C" void kernel_launch(void* const* d_in, const int* in_sizes, int n_in,
                              void* d_out, int out_size)
{
    const float* q_norm     = (const float*)d_in[0];
    const float* attn_local = (const float*)d_in[1];
    const float* v_local    = (const float*)d_in[2];
    const float* tokens     = (const float*)d_in[3];
    const float* bias       = (const float*)d_in[4];
    float* out = (float*)d_out;

    attn_gemv_rt<<<(B_ * NH_ * N_) / GR, THREADS>>>(q_norm, attn_local, tokens, bias);
    av_stream_kernel<<<(B_ * NH_ * N_) / ROWS, THREADS>>>(v_local, out);
}

// round 14
// speedup vs baseline: 1.2302x; 1.2302x over previous
#include <cuda_runtime.h>
#include <cstdint>

#define B_    2
#define NH_   8
#define N_    4096
#define D_    64
#define K2_   49
#define V_F4  784          // D*K2/4
#define THREADS 128
#define ROWS  8            // rows per CTA (8 | 4096 so h constant per CTA)

__device__ __forceinline__ uint32_t smem_u32(const void* p) {
    return (uint32_t)__cvta_generic_to_shared(p);
}
__device__ __forceinline__ void cp16(uint32_t dst, const void* src) {
    // .cg: v_local is pure streaming, keep it out of L1
    asm volatile("cp.async.cg.shared.global [%0], [%1], 16;\n" :: "r"(dst), "l"(src));
}
__device__ __forceinline__ void cp4(uint32_t dst, const void* src) {
    asm volatile("cp.async.ca.shared.global [%0], [%1], 4;\n" :: "r"(dst), "l"(src));
}
__device__ __forceinline__ void cp_commit() {
    asm volatile("cp.async.commit_group;\n" ::: "memory");
}
template <int NPend>
__device__ __forceinline__ void cp_wait() {
    asm volatile("cp.async.wait_group %0;\n" :: "n"(NPend) : "memory");
}

struct __align__(16) Stage {       // identical to R2's proven layout
    float4 v[V_F4];        // 12544 B
    float  q[D_];          // 256 B
    float  al[K2_];        // 196 B
    float  b[K2_];         // 196 B
    float  pad[2];         // sizeof = 13200
};

__global__ __launch_bounds__(THREADS)
void sw_attention_av_regtok(const float* __restrict__ q_norm,      // [B,NH,N,D]
                            const float* __restrict__ attn_local,  // [B,NH,N,K2]
                            const float* __restrict__ v_local,     // [B,NH,N,D,K2]
                            const float* __restrict__ tokens,      // [NH,D,K2]
                            const float* __restrict__ bias,        // [NH,N,K2]
                            float* __restrict__ out)               // [B,NH,N,D]
{
    __shared__ Stage st[2];             // 26400 B
    __shared__ float s_part[2][64];     // 512 B   (d-half partial sums, indexed by k)
    __shared__ float s_attn[K2_];       // 196 B

    const int t    = threadIdx.x;
    const int warp = t >> 5;
    const int lane = t & 31;
    const int row0 = blockIdx.x * ROWS;
    const int h    = (row0 >> 12) & (NH_ - 1);

    // warp -> (k-half, d-half) quadrant
    const int  kbase  = (warp >> 1) << 5;        // w0,w1:0  w2,w3:32
    const int  dhalf  = warp & 1;
    const int  dbase  = dhalf << 5;
    const int  k      = kbase + lane;
    const bool kvalid = (k < K2_);

    auto prefetch = [&](int s, int row) {        // R2's exact producer
        const float4* vrow = reinterpret_cast<const float4*>(v_local) + (size_t)row * V_F4;
        uint32_t vdst = smem_u32(st[s].v);
#pragma unroll
        for (int i = 0; i < 6; i++)
            cp16(vdst + (uint32_t)(t + THREADS * i) * 16u, vrow + t + THREADS * i);
        if (t < V_F4 - 6 * THREADS)
            cp16(vdst + (uint32_t)(t + 6 * THREADS) * 16u, vrow + t + 6 * THREADS);

        if (t < D_ / 4)
            cp16(smem_u32(st[s].q) + (uint32_t)t * 16u,
                 reinterpret_cast<const float4*>(q_norm + (size_t)row * D_) + t);

        if (t < K2_) {
            const int n = row & (N_ - 1);
            cp4(smem_u32(st[s].al) + (uint32_t)t * 4u, attn_local + (size_t)row * K2_ + t);
            cp4(smem_u32(st[s].b)  + (uint32_t)t * 4u, bias + ((size_t)h * N_ + n) * K2_ + t);
        }
        cp_commit();
    };

    prefetch(0, row0);                           // v0 streaming first

    // ---- hoist tokens into registers: ONE coalesced load pass per CTA
    // (replaces 1024 per-row LDG warp-instrs with 128 one-time ones)
    float tk[32];
    {
        const float* tokh = tokens + h * (D_ * K2_);
#pragma unroll
        for (int i = 0; i < 32; i++)
            tk[i] = kvalid ? __ldg(tokh + (dbase + i) * K2_ + k) : 0.f;
    }

    for (int r = 0; r < ROWS; r++) {
        if (r + 1 < ROWS) {
            prefetch((r + 1) & 1, row0 + r + 1);
            cp_wait<1>();                        // stage r complete (FIFO)
        } else {
            cp_wait<0>();
        }
        __syncthreads();                         // stage r&1 visible

        const Stage& S = st[r & 1];

        // ---- phase 1a: per-warp partial dot over its 32 d's (LSU-free: LDS only)
        {
            const float4* q4 = reinterpret_cast<const float4*>(S.q + dbase);
            float p0 = 0.f, p1 = 0.f;
#pragma unroll
            for (int c = 0; c < 8; c++) {        // LDS.128 broadcast
                const float4 qv = q4[c];
                p0 = fmaf(qv.x, tk[4 * c + 0], p0);
                p1 = fmaf(qv.y, tk[4 * c + 1], p1);
                p0 = fmaf(qv.z, tk[4 * c + 2], p0);
                p1 = fmaf(qv.w, tk[4 * c + 3], p1);
            }
            if (kvalid) s_part[dhalf][k] = p0 + p1;
        }
        __syncthreads();                         // partials visible

        // ---- phase 1b: combine halves + bias + attn_local
        if (t < K2_)
            s_attn[t] = s_part[0][t] + s_part[1][t] + S.al[t] + S.b[t];
        __syncthreads();                         // attn visible

        // ---- phase 2: out[d] = sum_k attn[k] * v[d,k]  (stride-49: conflict-free)
        if (t < D_) {
            const float* vd = reinterpret_cast<const float*>(S.v) + t * K2_;
            float acc0 = 0.f, acc1 = 0.f;
#pragma unroll
            for (int kk = 0; kk < 48; kk += 2) {
                acc0 = fmaf(s_attn[kk + 0], vd[kk + 0], acc0);
                acc1 = fmaf(s_attn[kk + 1], vd[kk + 1], acc1);
            }
            acc0 = fmaf(s_attn[48], vd[48], acc0);
            out[(size_t)(row0 + r) * D_ + t] = acc0 + acc1;
        }

        __syncthreads();                         // readers done -> slot reusable
    }
}

extern "C" void kernel_launch(void* const* d_in, const int* in_sizes, int n_in,
                              void* d_out, int out_size)
{
    const float* q_norm     = (const float*)d_in[0];
    const float* attn_local = (const float*)d_in[1];
    const float* v_local    = (const float*)d_in[2];
    const float* tokens     = (const float*)d_in[3];
    const float* bias       = (const float*)d_in[4];
    float* out = (float*)d_out;

    const int blocks = (B_ * NH_ * N_) / ROWS;   // 8192
    sw_attention_av_regtok<<<blocks, THREADS>>>(q_norm, attn_local, v_local,
                                                tokens, bias, out);
}

// round 15
// speedup vs baseline: 1.2680x; 1.0307x over previous
#include <cuda_runtime.h>
#include <cstdint>

#define B_    2
#define NH_   8
#define N_    4096
#define D_    64
#define K2_   49
#define V_BYTES 12544      // D*K2*4, 16B multiple
#define V_F4  784
#define THREADS 128
#define ROWS  8            // rows per CTA (8 | 4096 so h constant per CTA)

__device__ __forceinline__ uint32_t smem_u32(const void* p) {
    return (uint32_t)__cvta_generic_to_shared(p);
}
__device__ __forceinline__ void cp16(uint32_t dst, const void* src) {
    asm volatile("cp.async.cg.shared.global [%0], [%1], 16;\n" :: "r"(dst), "l"(src));
}
__device__ __forceinline__ void cp4(uint32_t dst, const void* src) {
    asm volatile("cp.async.ca.shared.global [%0], [%1], 4;\n" :: "r"(dst), "l"(src));
}
__device__ __forceinline__ void cp_commit() {
    asm volatile("cp.async.commit_group;\n" ::: "memory");
}
template <int NPend>
__device__ __forceinline__ void cp_wait() {
    asm volatile("cp.async.wait_group %0;\n" :: "n"(NPend) : "memory");
}
__device__ __forceinline__ void mbar_init(uint32_t a, uint32_t cnt) {
    asm volatile("mbarrier.init.shared.b64 [%0], %1;" :: "r"(a), "r"(cnt) : "memory");
}
__device__ __forceinline__ void mbar_expect_tx(uint32_t a, uint32_t bytes) {
    asm volatile("mbarrier.arrive.expect_tx.shared.b64 _, [%0], %1;"
                 :: "r"(a), "r"(bytes) : "memory");
}
__device__ __forceinline__ void bulk_g2s(uint32_t dst, const void* src,
                                         uint32_t bytes, uint32_t mbar) {
    asm volatile(
        "cp.async.bulk.shared::cta.global.mbarrier::complete_tx::bytes "
        "[%0], [%1], %2, [%3];"
        :: "r"(dst), "l"(src), "r"(bytes), "r"(mbar) : "memory");
}
__device__ __forceinline__ void mbar_wait(uint32_t a, uint32_t parity) {
    asm volatile(
        "{\n\t.reg .pred P;\n\t"
        "WL_%=:\n\t"
        "mbarrier.try_wait.parity.acquire.cta.shared::cta.b64 P, [%0], %1, 0x989680;\n\t"
        "@P bra.uni WD_%=;\n\t"
        "bra.uni WL_%=;\n\t"
        "WD_%=:\n\t}"
        :: "r"(a), "r"(parity) : "memory");
}

struct __align__(16) Stage {
    float4 v[V_F4];        // 12544 B
    float  q[D_];          // 256 B
    float  al[K2_];        // 196 B
    float  b[K2_];         // 196 B
    float  pad[2];         // sizeof = 13200
};

__global__ __launch_bounds__(THREADS)
void sw_attention_av_bulk(const float* __restrict__ q_norm,      // [B,NH,N,D]
                          const float* __restrict__ attn_local,  // [B,NH,N,K2]
                          const float* __restrict__ v_local,     // [B,NH,N,D,K2]
                          const float* __restrict__ tokens,      // [NH,D,K2]
                          const float* __restrict__ bias,        // [NH,N,K2]
                          float* __restrict__ out)               // [B,NH,N,D]
{
    __shared__ Stage    st[2];           // 26400 B
    __shared__ uint64_t mbar[2];
    __shared__ float    s_part[2][64];   // d-half partials, indexed by k
    __shared__ float    s_attn[K2_];

    const int t    = threadIdx.x;
    const int warp = t >> 5;
    const int lane = t & 31;
    const int row0 = blockIdx.x * ROWS;
    const int h    = (row0 >> 12) & (NH_ - 1);

    // warp -> (k-half, d-half) quadrant for phase 1
    const int  kbase  = (warp >> 1) << 5;
    const int  dhalf  = warp & 1;
    const int  dbase  = dhalf << 5;
    const int  k      = kbase + lane;
    const bool kvalid = (k < K2_);

    if (t == 0) { mbar_init(smem_u32(&mbar[0]), 1); mbar_init(smem_u32(&mbar[1]), 1); }
    __syncthreads();

    // v tile: single bulk copy per row, issued by thread 0 (off the LSU path)
    auto prefetch_v = [&](int s, int row) {
        if (t == 0) {
            mbar_expect_tx(smem_u32(&mbar[s]), V_BYTES);
            bulk_g2s(smem_u32(st[s].v),
                     reinterpret_cast<const char*>(v_local) + (size_t)row * V_BYTES,
                     V_BYTES, smem_u32(&mbar[s]));
        }
    };
    // small operands (q / attn_local / bias) via cp.async group
    auto prefetch_small = [&](int s, int row) {
        if (t < D_ / 4)
            cp16(smem_u32(st[s].q) + (uint32_t)t * 16u,
                 reinterpret_cast<const float4*>(q_norm + (size_t)row * D_) + t);
        if (t < K2_) {
            const int n = row & (N_ - 1);
            cp4(smem_u32(st[s].al) + (uint32_t)t * 4u, attn_local + (size_t)row * K2_ + t);
            cp4(smem_u32(st[s].b)  + (uint32_t)t * 4u, bias + ((size_t)h * N_ + n) * K2_ + t);
        }
        cp_commit();
    };

    prefetch_small(0, row0);
    prefetch_v(0, row0);

    // ---- hoist tokens into registers (once per CTA; coalesced)
    float tk[32];
    {
        const float* tokh = tokens + h * (D_ * K2_);
#pragma unroll
        for (int i = 0; i < 32; i++)
            tk[i] = kvalid ? __ldg(tokh + (dbase + i) * K2_ + k) : 0.f;
    }

    for (int r = 0; r < ROWS; r++) {
        if (r + 1 < ROWS) {
            prefetch_small((r + 1) & 1, row0 + r + 1);
            prefetch_v((r + 1) & 1, row0 + r + 1);
            cp_wait<1>();                          // this thread's small group r done
        } else {
            cp_wait<0>();
        }
        mbar_wait(smem_u32(&mbar[r & 1]), (uint32_t)((r >> 1) & 1));  // v tile r done
        __syncthreads();                           // all threads' small slices visible

        const Stage& S = st[r & 1];

        // ---- phase 1a: quadrant partial dot (registers x LDS broadcast)
        {
            const float4* q4 = reinterpret_cast<const float4*>(S.q + dbase);
            float p0 = 0.f, p1 = 0.f;
#pragma unroll
            for (int c = 0; c < 8; c++) {
                const float4 qv = q4[c];
                p0 = fmaf(qv.x, tk[4 * c + 0], p0);
                p1 = fmaf(qv.y, tk[4 * c + 1], p1);
                p0 = fmaf(qv.z, tk[4 * c + 2], p0);
                p1 = fmaf(qv.w, tk[4 * c + 3], p1);
            }
            if (kvalid) s_part[dhalf][k] = p0 + p1;
        }
        __syncthreads();

        // ---- phase 1b: combine halves + bias + attn_local
        if (t < K2_)
            s_attn[t] = s_part[0][t] + s_part[1][t] + S.al[t] + S.b[t];
        __syncthreads();

        // ---- phase 2: out[d] = sum_k attn[k] * v[d,k]
        if (t < D_) {
            const float* vd = reinterpret_cast<const float*>(S.v) + t * K2_;
            float acc0 = 0.f, acc1 = 0.f;
#pragma unroll
            for (int kk = 0; kk < 48; kk += 2) {
                acc0 = fmaf(s_attn[kk + 0], vd[kk + 0], acc0);
                acc1 = fmaf(s_attn[kk + 1], vd[kk + 1], acc1);
            }
            acc0 = fmaf(s_attn[48], vd[48], acc0);
            out[(size_t)(row0 + r) * D_ + t] = acc0 + acc1;
        }

        __syncthreads();    // readers done -> slot r&1 and its mbar reusable
    }
}

extern "C" void kernel_launch(void* const* d_in, const int* in_sizes, int n_in,
                              void* d_out, int out_size)
{
    const float* q_norm     = (const float*)d_in[0];
    const float* attn_local = (const float*)d_in[1];
    const float* v_local    = (const float*)d_in[2];
    const float* tokens     = (const float*)d_in[3];
    const float* bias       = (const float*)d_in[4];
    float* out = (float*)d_out;

    const int blocks = (B_ * NH_ * N_) / ROWS;   // 8192
    sw_attention_av_bulk<<<blocks, THREADS>>>(q_norm, attn_local, v_local,
                                              tokens, bias, out);
}